// round 17
// baseline (speedup 1.0000x reference)
#include <cuda_runtime.h>

#define NBLK 144
#define NTHR 256
#define LDS_ 132   // padded smem row stride (floats); 132 % 32 == 4 -> float4 lane-rows conflict-free
#define LDP2 516   // P2 row stride for K=512 buffers; 516 % 32 == 4 -> same class
typedef unsigned long long u64;

// Scratch (allocation-free rule: __device__ globals)
__device__ float g_r[512 * 512];     // relu((x@fp_W+fp_b) @ gat_W^T)
__device__ float g_opWt[128 * 512];  // op_W transposed: [n][k]
__device__ unsigned g_cnt = 0;       // barrier arrivals (returns to 0 every launch)
__device__ unsigned g_gen = 0;       // barrier generation (monotonic across launches — fine)

__device__ __forceinline__ void grid_barrier()
{
    __threadfence();
    __syncthreads();
    if (threadIdx.x == 0) {
        unsigned gen = *(volatile unsigned*)&g_gen;   // read BEFORE arriving
        unsigned t = atomicAdd(&g_cnt, 1u);
        if (t == NBLK - 1) {
            g_cnt = 0;
            __threadfence();
            atomicAdd(&g_gen, 1u);                    // release
        } else {
            while (*(volatile unsigned*)&g_gen == gen) { }
        }
    }
    __syncthreads();
}

__device__ __forceinline__ u64 ffma2(u64 a, u64 b, u64 c) {
    u64 d;
    asm("fma.rn.f32x2 %0, %1, %2, %3;" : "=l"(d) : "l"(a), "l"(b), "l"(c));
    return d;
}
__device__ __forceinline__ float f2lo(u64 v) { return __uint_as_float((unsigned)v); }
__device__ __forceinline__ float f2hi(u64 v) { return __uint_as_float((unsigned)(v >> 32)); }

// Warp tile 16m x 64n over NK4*4 k-values. A rows broadcast; B lane-strided.
template<int NK4, int LDA, int LDB>
__device__ __forceinline__ void wtile16m(const float* __restrict__ As,
                                         const float* __restrict__ Bs,
                                         int lane, u64 acc[16][2])
{
    #pragma unroll
    for (int k4 = 0; k4 < NK4; k4++) {
        ulonglong2 b0 = *(const ulonglong2*)(Bs + (size_t)lane        * LDB + k4 * 4);
        ulonglong2 b1 = *(const ulonglong2*)(Bs + (size_t)(lane + 32) * LDB + k4 * 4);
        #pragma unroll
        for (int i = 0; i < 16; i++) {
            ulonglong2 a = *(const ulonglong2*)(As + (size_t)i * LDA + k4 * 4);
            acc[i][0] = ffma2(a.x, b0.x, acc[i][0]);
            acc[i][0] = ffma2(a.y, b0.y, acc[i][0]);
            acc[i][1] = ffma2(a.x, b1.x, acc[i][1]);
            acc[i][1] = ffma2(a.y, b1.y, acc[i][1]);
        }
    }
}

// Warp tile 8m x 64n over NK4*4 k-values.
template<int NK4, int LDA, int LDB>
__device__ __forceinline__ void wtile8m(const float* __restrict__ As,
                                        const float* __restrict__ Bs,
                                        int lane, u64 acc[8][2])
{
    #pragma unroll
    for (int k4 = 0; k4 < NK4; k4++) {
        ulonglong2 b0 = *(const ulonglong2*)(Bs + (size_t)lane        * LDB + k4 * 4);
        ulonglong2 b1 = *(const ulonglong2*)(Bs + (size_t)(lane + 32) * LDB + k4 * 4);
        #pragma unroll
        for (int i = 0; i < 8; i++) {
            ulonglong2 a = *(const ulonglong2*)(As + (size_t)i * LDA + k4 * 4);
            acc[i][0] = ffma2(a.x, b0.x, acc[i][0]);
            acc[i][0] = ffma2(a.y, b0.y, acc[i][0]);
            acc[i][1] = ffma2(a.x, b1.x, acc[i][1]);
            acc[i][1] = ffma2(a.y, b1.y, acc[i][1]);
        }
    }
}

__global__ void __launch_bounds__(NTHR, 1)
fused_kernel(const float* __restrict__ x,   const float* __restrict__ mask,
             const float* __restrict__ emb, const float* __restrict__ gatW,
             const float* __restrict__ fpW, const float* __restrict__ fpb,
             const float* __restrict__ opW, const float* __restrict__ opb,
             const int*   __restrict__ kp,  float* __restrict__ out)
{
    extern __shared__ float sm[];
    const int blk = blockIdx.x, t = threadIdx.x, lane = t & 31, w = t >> 5;

    // ═ Phase A ═══════════════════════════════════════════════════════════════
    if (blk < 128) {
        // Block (m-group, c): compute OWN h0 tile [32m x 128f] in smem (no
        // producer barrier), then r tile [32m x 64c] -> g_r. 
        const int m0 = (blk >> 3) * 32, c0 = (blk & 7) * 64;
        float* As_x  = sm;                // 32 x LDS_   (x tile)
        float* Bs_fp = sm + 32 * LDS_;    // 128 x LDS_  (fp_W^T: [n][f])
        float* h0s   = sm + 160 * LDS_;   // 32 x LDS_   (h0 tile, stays in smem)
        float* Bs_g  = sm + 192 * LDS_;   // 64 x LDS_   (gat_W rows c0..c0+64)
        float* Pb    = sm + 256 * LDS_;   // 8 bufs x 1040

        #pragma unroll
        for (int i = 0; i < 4; i++) {
            int idx = t + i * 256; int r = idx >> 5, c4 = idx & 31;
            *(float4*)(As_x + r * LDS_ + c4 * 4) =
                *(const float4*)(x + (size_t)(m0 + r) * 128 + c4 * 4);
        }
        #pragma unroll
        for (int i = 0; i < 8; i++) {
            int idx = t + i * 256; int r = idx >> 5, c4 = idx & 31;
            *(float4*)(Bs_g + r * LDS_ + c4 * 4) =
                *(const float4*)(gatW + (size_t)(c0 + r) * 128 + c4 * 4);
        }
        {   // transpose fp_W (all 128 n): thread (kk, half) owns f-row kk, n half
            int kk = t & 127, half = t >> 7;
            #pragma unroll
            for (int p4 = 0; p4 < 16; p4++) {
                float4 v = *(const float4*)(fpW + (size_t)kk * 128 + half * 64 + p4 * 4);
                int n = half * 64 + p4 * 4;
                Bs_fp[(n + 0) * LDS_ + kk] = v.x;
                Bs_fp[(n + 1) * LDS_ + kk] = v.y;
                Bs_fp[(n + 2) * LDS_ + kk] = v.z;
                Bs_fp[(n + 3) * LDS_ + kk] = v.w;
            }
        }
        __syncthreads();

        // h0 = x @ fp_W + fp_b. Warp = (mh: 16 rows) x (nh: 64 cols) x (kh: K=64 half)
        {
            const int mh = w & 1, nh = (w >> 1) & 1, kh = w >> 2;
            u64 acc[16][2];
            #pragma unroll
            for (int i = 0; i < 16; i++) { acc[i][0] = 0ull; acc[i][1] = 0ull; }
            wtile16m<16, LDS_, LDS_>(As_x + (size_t)(mh * 16) * LDS_ + kh * 64,
                                     Bs_fp + (size_t)(nh * 64) * LDS_ + kh * 64, lane, acc);
            float* P = Pb + w * 1040;
            #pragma unroll
            for (int i = 0; i < 16; i++)
                #pragma unroll
                for (int j = 0; j < 2; j++)
                    P[i * 64 + lane + 32 * j] = f2lo(acc[i][j]) + f2hi(acc[i][j]);
        }
        __syncthreads();
        // reduce 2 K-halves + fp_b -> h0s; 1024 float4 outputs, 4 per thread
        #pragma unroll
        for (int q = 0; q < 4; q++) {
            int id = t + q * 256;            // 0..1023 over (m 0..31) x (n4 0..31)
            int m = id >> 5, n4 = id & 31;
            int mh2 = m >> 4, i = m & 15, nh2 = n4 >> 4, p4 = n4 & 15;
            const float* Pa = Pb + (size_t)(mh2 + 2 * nh2) * 1040 + i * 64 + p4 * 4;
            float4 v = *(const float4*)Pa;
            float4 p = *(const float4*)(Pa + 4 * 1040);
            float4 b = *(const float4*)(fpb + n4 * 4);
            v.x += p.x + b.x; v.y += p.y + b.y;
            v.z += p.z + b.z; v.w += p.w + b.w;
            *(float4*)(h0s + (size_t)m * LDS_ + n4 * 4) = v;
        }
        __syncthreads();

        // r = relu(h0 @ gat_W^T). Warp = (mh: 16 rows) x (kq: K=32 quarter); 4-way reduce.
        {
            const int mh = w & 1, kq = w >> 1;
            u64 acc[16][2];
            #pragma unroll
            for (int i = 0; i < 16; i++) { acc[i][0] = 0ull; acc[i][1] = 0ull; }
            wtile16m<8, LDS_, LDS_>(h0s + (size_t)(mh * 16) * LDS_ + kq * 32,
                                    Bs_g + kq * 32, lane, acc);
            float* P = Pb + w * 1040;
            #pragma unroll
            for (int i = 0; i < 16; i++)
                #pragma unroll
                for (int j = 0; j < 2; j++)
                    P[i * 64 + lane + 32 * j] = f2lo(acc[i][j]) + f2hi(acc[i][j]);
        }
        __syncthreads();
        #pragma unroll
        for (int q = 0; q < 2; q++) {
            int id = t + q * 256;            // 0..511
            int mh2 = id >> 8, e4 = id & 255;
            int i = e4 >> 4, n4 = (e4 & 15) * 4;
            float4 v = *(const float4*)(Pb + (size_t)mh2 * 1040 + i * 64 + n4);
            #pragma unroll
            for (int kk = 1; kk < 4; kk++) {
                float4 p = *(const float4*)(Pb + (size_t)(2 * kk + mh2) * 1040 + i * 64 + n4);
                v.x += p.x; v.y += p.y; v.z += p.z; v.w += p.w;
            }
            v.x = fmaxf(v.x, 0.f); v.y = fmaxf(v.y, 0.f);
            v.z = fmaxf(v.z, 0.f); v.w = fmaxf(v.w, 0.f);
            *(float4*)(g_r + (size_t)(m0 + mh2 * 16 + i) * 512 + c0 + n4) = v;
        }
    } else {
        // Blocks 128..143: opWt slice + adjacency (8 rows each; fully independent)
        const int a = blk - 128;             // 0..15
        {   // opW transpose: k-slice [a*32, a*32+32); thread = (n, half)
            int k0 = a * 32;
            int n = t & 127, half = t >> 7;
            float v[16];
            #pragma unroll
            for (int kk = 0; kk < 16; kk++)
                v[kk] = opW[(size_t)(k0 + half * 16 + kk) * 128 + n];
            #pragma unroll
            for (int q = 0; q < 4; q++)
                *(float4*)(g_opWt + (size_t)n * 512 + k0 + half * 16 + q * 4) =
                    make_float4(v[q * 4], v[q * 4 + 1], v[q * 4 + 2], v[q * 4 + 3]);
        }
        // adjacency rows [a*8, a*8+8): 4 passes of 2 rows (rr = thread half)
        float* es    = sm;                   // 128 x LDS_
        float* s_n2  = sm + 128 * LDS_;      // 128
        float* s_sim = s_n2 + 128;           // 2 x 128
        #pragma unroll
        for (int i = 0; i < 16; i++) {
            int idx = t + i * 256; int r = idx >> 5, c4 = idx & 31;
            *(float4*)(es + r * LDS_ + c4 * 4) =
                *(const float4*)(emb + (size_t)r * 128 + c4 * 4);
        }
        __syncthreads();
        const int rr = t >> 7, j = t & 127;
        const float* ej = es + j * LDS_;
        {   // norms once (both halves compute; half 0 stores)
            float nn = 0.f;
            #pragma unroll 8
            for (int f4 = 0; f4 < 32; f4++) {
                float4 b = *(const float4*)(ej + f4 * 4);
                nn += b.x * b.x + b.y * b.y + b.z * b.z + b.w * b.w;
            }
            if (rr == 0) s_n2[j] = nn;
        }
        __syncthreads();
        const int k = kp[0], start = a * 8;
        #pragma unroll
        for (int p = 0; p < 4; p++) {
            const int irow = start + p * 2 + rr;
            const float* ei = es + irow * LDS_;
            float dij = 0.f;
            #pragma unroll 8
            for (int f4 = 0; f4 < 32; f4++) {
                float4 b = *(const float4*)(ej + f4 * 4);
                float4 a4 = *(const float4*)(ei + f4 * 4);
                dij += a4.x * b.x + a4.y * b.y + a4.z * b.z + a4.w * b.w;
            }
            float sim = dij / (sqrtf(s_n2[irow]) * sqrtf(s_n2[j]));
            s_sim[rr * 128 + j] = sim;
            __syncthreads();
            const float4* S = (const float4*)(s_sim + rr * 128);
            int cnt = 0;
            #pragma unroll 8
            for (int q = 0; q < 32; q++) {
                float4 s4 = S[q];
                int base = q * 4;
                cnt += (s4.x > sim) || (s4.x == sim && base + 0 < j);
                cnt += (s4.y > sim) || (s4.y == sim && base + 1 < j);
                cnt += (s4.z > sim) || (s4.z == sim && base + 2 < j);
                cnt += (s4.w > sim) || (s4.w == sim && base + 3 < j);
            }
            out[65536 + irow * 128 + j] = (cnt < k) ? 1.0f : 0.0f;
            __syncthreads();                 // s_sim reused next pass
        }
    }

    grid_barrier();                          // the ONLY grid-wide sync

    // ═ Phase B (P2, proven): out = x(1-mask) + (r @ op_W + op_b)·mask,
    //   tile [8m x 64n], 8-way K-split: warp w owns k in [64w, 64w+64) ════════
    if (blk < 128) {
        float* As = sm;                        // 8 x LDP2
        float* Bs = sm + 8 * LDP2;             // 64 x LDP2
        float* Pb = sm + 8 * LDP2 + 64 * LDP2; // 8 x 520
        const int m0 = (blk >> 1) * 8, n0 = (blk & 1) * 64;

        #pragma unroll
        for (int i = 0; i < 4; i++) {
            int idx = lane + 32 * i;           // (row 0..7) x (c4 0..15)
            int row = idx >> 4, c4 = idx & 15;
            *(float4*)(As + (size_t)row * LDP2 + w * 64 + c4 * 4) =
                *(const float4*)(g_r + (size_t)(m0 + row) * 512 + w * 64 + c4 * 4);
        }
        #pragma unroll
        for (int i = 0; i < 32; i++) {
            int idx = lane + 32 * i;           // (row 0..63) x (c4 0..15)
            int row = idx >> 4, c4 = idx & 15;
            *(float4*)(Bs + (size_t)row * LDP2 + w * 64 + c4 * 4) =
                *(const float4*)(g_opWt + (size_t)(n0 + row) * 512 + w * 64 + c4 * 4);
        }
        __syncwarp();
        u64 acc[8][2];
        #pragma unroll
        for (int i = 0; i < 8; i++) { acc[i][0] = 0ull; acc[i][1] = 0ull; }
        wtile8m<16, LDP2, LDP2>(As + w * 64, Bs + w * 64, lane, acc);
        float* P = Pb + w * 520;
        #pragma unroll
        for (int i = 0; i < 8; i++)
            #pragma unroll
            for (int j = 0; j < 2; j++)
                P[i * 64 + lane + 32 * j] = f2lo(acc[i][j]) + f2hi(acc[i][j]);
        __syncthreads();
        {
            int o = t * 2;                     // 0..510
            int m = o >> 6, n = o & 63;
            float v0 = 0.f, v1 = 0.f;
            #pragma unroll
            for (int ww = 0; ww < 8; ww++) {
                const float* p = Pb + (size_t)ww * 520 + o;
                v0 += p[0]; v1 += p[1];
            }
            v0 += opb[n0 + n]; v1 += opb[n0 + n + 1];
            size_t gi = (size_t)(m0 + m) * 128 + n0 + n;
            float2 xv = *(const float2*)(x + gi);
            float2 mv = *(const float2*)(mask + gi);
            float2 ov;
            ov.x = xv.x * (1.0f - mv.x) + v0 * mv.x;
            ov.y = xv.y * (1.0f - mv.y) + v1 * mv.y;
            *(float2*)(out + gi) = ov;
        }
    }
}

extern "C" void kernel_launch(void* const* d_in, const int* in_sizes, int n_in,
                              void* d_out, int out_size)
{
    const float* x    = (const float*)d_in[0];
    const float* mask = (const float*)d_in[1];
    const float* emb  = (const float*)d_in[2];
    const float* gatW = (const float*)d_in[3];
    // d_in[4] = gat_a: provably unused (softmax over constant logits -> adj/k; rows sum to 1)
    const float* fpW  = (const float*)d_in[5];
    const float* fpb  = (const float*)d_in[6];
    const float* opW  = (const float*)d_in[7];
    const float* opb  = (const float*)d_in[8];
    const int*   kp   = (const int*)d_in[9];
    float* out = (float*)d_out;

    // Phase A r-block layout is the max: 256*LDS_ + 8*1040 = 42112 floats = 168448 B
    const int SMEM = (256 * LDS_ + 8 * 1040) * 4;
    cudaFuncSetAttribute(fused_kernel, cudaFuncAttributeMaxDynamicSharedMemorySize, SMEM);
    fused_kernel<<<NBLK, NTHR, SMEM>>>(x, mask, emb, gatW, fpW, fpb, opW, opb, kp, out);
}